// round 16
// baseline (speedup 1.0000x reference)
#include <cuda_runtime.h>
#include <cuda_bf16.h>
#include <cstdint>
#include <math.h>

// ---------------- constants ----------------
// B=16, N=1024, T=12, F=1, D_MODEL=512, D_K=D_V=32, H=3, K=3, C=32

// ---------------- scratch (static device memory; no allocation) ----------------
__device__ float g_TEmx[16 * 12 * 1024];      // (B,T,N)
__device__ float g_qkvp[4 * 16 * 12 * 288];   // partial QKV per n-quarter
__device__ float g_ctx [16 * 12 * 96];        // (B,T,96)
__device__ float g_TAT [16 * 12 * 1024];      // (B,T,N)
__device__ float g_SEmx[16 * 1024 * 512];     // (B,N,512)
__device__ float g_QKs [16 * 1024 * 192];     // (B,N,192): 0..95 = Qs, 96..191 = Ks
__device__ unsigned long long g_Wr2[32 * 15 * 32];    // {wa,wb} per (ci,pos,c)
__device__ unsigned long long g_bc [3 * 1024 * 1024]; // {adj*cmask, cheb} per (k,m,j)
__device__ unsigned long long g_part[4 * 7 * 49152];  // spatial partials [quarter][slot][jidx]

// ---------------- f32x2 helpers ----------------
__device__ __forceinline__ unsigned long long pk2(float a, float b) {
    unsigned long long r; asm("mov.b64 %0, {%1,%2};" : "=l"(r) : "f"(a), "f"(b)); return r;
}
__device__ __forceinline__ void unpk(unsigned long long v, float& a, float& b) {
    asm("mov.b64 {%0,%1}, %2;" : "=f"(a), "=f"(b) : "l"(v));
}
__device__ __forceinline__ unsigned long long ffma2(unsigned long long a, unsigned long long b, unsigned long long c) {
    unsigned long long d; asm("fma.rn.f32x2 %0, %1, %2, %3;" : "=l"(d) : "l"(a), "l"(b), "l"(c)); return d;
}
__device__ __forceinline__ unsigned long long mul2(unsigned long long a, unsigned long long b) {
    unsigned long long d; asm("mul.rn.f32x2 %0, %1, %2;" : "=l"(d) : "l"(a), "l"(b)); return d;
}
__device__ __forceinline__ unsigned long long add2(unsigned long long a, unsigned long long b) {
    unsigned long long d; asm("add.rn.f32x2 %0, %1, %2;" : "=l"(d) : "l"(a), "l"(b)); return d;
}
__device__ __forceinline__ unsigned int to_tf32(float f) {
    unsigned int r; asm("cvt.rna.tf32.f32 %0, %1;" : "=r"(r) : "f"(f)); return r;
}
#define MMA_TF32(c, A, B)                                                      \
    asm volatile("mma.sync.aligned.m16n8k8.row.col.f32.tf32.tf32.f32 "         \
        "{%0,%1,%2,%3}, {%4,%5,%6,%7}, {%8,%9}, {%0,%1,%2,%3};"                \
        : "+f"((c)[0]), "+f"((c)[1]), "+f"((c)[2]), "+f"((c)[3])               \
        : "r"((A)[0]), "r"((A)[1]), "r"((A)[2]), "r"((A)[3]),                  \
          "r"((B)[0]), "r"((B)[1]))

// ---------------- helpers ----------------
__device__ __forceinline__ void block_reduce2(float& s, float& s2, float* shm) {
    #pragma unroll
    for (int o = 16; o > 0; o >>= 1) {
        s  += __shfl_down_sync(0xFFFFFFFFu, s,  o);
        s2 += __shfl_down_sync(0xFFFFFFFFu, s2, o);
    }
    int nw = blockDim.x >> 5;
    int w = threadIdx.x >> 5, l = threadIdx.x & 31;
    if (l == 0) { shm[w] = s; shm[w + 32] = s2; }
    __syncthreads();
    if (w == 0) {
        s  = (l < nw) ? shm[l] : 0.f;
        s2 = (l < nw) ? shm[l + 32] : 0.f;
        #pragma unroll
        for (int o = 16; o > 0; o >>= 1) {
            s  += __shfl_down_sync(0xFFFFFFFFu, s,  o);
            s2 += __shfl_down_sync(0xFFFFFFFFu, s2, o);
        }
        if (l == 0) { shm[0] = s; shm[1] = s2; }
    }
    __syncthreads();
    s = shm[0]; s2 = shm[1];
}

// ---------------- K1: temporal embed + LN over N (all-coalesced; thread = n) ----------------
__global__ void __launch_bounds__(1024) k_temporal_ln(
        const float* __restrict__ x, const float* __restrict__ peT,
        const float* __restrict__ gT, const float* __restrict__ bT) {
    int b = blockIdx.x;            // 16 blocks
    int n = threadIdx.x;           // 1024 threads
    __shared__ float red[32][24];
    __shared__ float stats[24];

    float v[12];
    {
        const float4* xr = (const float4*)(x + ((size_t)b * 1024 + n) * 12);
        float4 x0 = xr[0], x1 = xr[1], x2 = xr[2];
        v[0]=x0.x; v[1]=x0.y; v[2]=x0.z; v[3]=x0.w;
        v[4]=x1.x; v[5]=x1.y; v[6]=x1.z; v[7]=x1.w;
        v[8]=x2.x; v[9]=x2.y; v[10]=x2.z; v[11]=x2.w;
    }
    #pragma unroll
    for (int t = 0; t < 12; t++) v[t] += peT[t * 1024 + n];

    float pv[12], qv[12];
    #pragma unroll
    for (int t = 0; t < 12; t++) { pv[t] = v[t]; qv[t] = v[t] * v[t]; }
    #pragma unroll
    for (int o = 16; o > 0; o >>= 1) {
        #pragma unroll
        for (int t = 0; t < 12; t++) {
            pv[t] += __shfl_xor_sync(0xFFFFFFFFu, pv[t], o);
            qv[t] += __shfl_xor_sync(0xFFFFFFFFu, qv[t], o);
        }
    }
    int w = threadIdx.x >> 5, l = threadIdx.x & 31;
    if (l == 0) {
        #pragma unroll
        for (int t = 0; t < 12; t++) { red[w][t] = pv[t]; red[w][12 + t] = qv[t]; }
    }
    __syncthreads();
    if (threadIdx.x < 24) {
        float acc = 0.f;
        #pragma unroll
        for (int ww = 0; ww < 32; ww++) acc += red[ww][threadIdx.x];
        stats[threadIdx.x] = acc;
    }
    __syncthreads();

    float gn = gT[n], bn = bT[n];
    #pragma unroll
    for (int t = 0; t < 12; t++) {
        float mu = stats[t] * (1.f / 1024.f);
        float var = stats[12 + t] * (1.f / 1024.f) - mu * mu;
        float rstd = rsqrtf(var + 1e-5f);
        g_TEmx[((size_t)b * 12 + t) * 1024 + n] = (v[t] - mu) * rstd * gn + bn;
    }
}

// ---------------- K2a: QKV projection partials; grid (16 b, 4 quarters), 288 thr ----------------
__global__ void k_qkv(const float* __restrict__ WQ, const float* __restrict__ WK,
                      const float* __restrict__ WV) {
    int b = blockIdx.x; int q = blockIdx.y;
    int tid = threadIdx.x;
    int n0 = q * 256;
    __shared__ unsigned long long Ep[6][256];   // pairs (2tp, 2tp+1)
    for (int i = tid; i < 1536; i += 288) {
        int tp = i >> 8; int nn = i & 255;
        float a = g_TEmx[((size_t)b * 12 + 2 * tp) * 1024 + n0 + nn];
        float c = g_TEmx[((size_t)b * 12 + 2 * tp + 1) * 1024 + n0 + nn];
        Ep[tp][nn] = pk2(a, c);
    }
    __syncthreads();
    const float* W; int cw;
    if (tid < 96)       { W = WQ; cw = tid; }
    else if (tid < 192) { W = WK; cw = tid - 96; }
    else                { W = WV; cw = tid - 192; }
    unsigned long long acc[6];
    #pragma unroll
    for (int i = 0; i < 6; i++) acc[i] = 0ull;
    #pragma unroll 4
    for (int nn = 0; nn < 256; nn++) {
        float wv = W[(n0 + nn) * 96 + cw];
        unsigned long long wp = pk2(wv, wv);
        #pragma unroll
        for (int tp = 0; tp < 6; tp++) acc[tp] = ffma2(Ep[tp][nn], wp, acc[tp]);
    }
    int qb = q * 55296 + b * 12 * 288;
    #pragma unroll
    for (int tp = 0; tp < 6; tp++) {
        float lo, hi; unpk(acc[tp], lo, hi);
        g_qkvp[qb + (2 * tp) * 288 + tid]     = lo;
        g_qkvp[qb + (2 * tp + 1) * 288 + tid] = hi;
    }
}

// ---------------- K2b: temporal attention per (b,h); sums quarter-partials; writes re_At ----------------
__global__ void k_tattn(const float* __restrict__ resa, float* __restrict__ reat) {
    int b = blockIdx.x / 3, h = blockIdx.x % 3;
    int tid = threadIdx.x;
    int t = tid >> 5, d = tid & 31;   // 384 threads = 12 warps x 32
    __shared__ float Q[12][32], Kt[12][32], V[12][32], S[12][12];

    int off = b * 3456 + t * 288 + h * 32 + d;
    Q [t][d] = g_qkvp[off]       + g_qkvp[off + 55296]       + g_qkvp[off + 110592]       + g_qkvp[off + 165888];
    Kt[t][d] = g_qkvp[off + 96]  + g_qkvp[off + 96 + 55296]  + g_qkvp[off + 96 + 110592]  + g_qkvp[off + 96 + 165888];
    V [t][d] = g_qkvp[off + 192] + g_qkvp[off + 192 + 55296] + g_qkvp[off + 192 + 110592] + g_qkvp[off + 192 + 165888];
    __syncthreads();

    if (tid < 144) {
        int qi = tid / 12, ki = tid % 12;
        float s = 0.f;
        #pragma unroll
        for (int dd = 0; dd < 32; dd++) s += Q[qi][dd] * Kt[ki][dd];
        s = s * 0.17677669529663687f + resa[((size_t)(b * 3 + h) * 12 + qi) * 12 + ki];
        S[qi][ki] = s;
        reat[((size_t)(b * 3 + h) * 12 + qi) * 12 + ki] = s;
    }
    __syncthreads();
    if (tid < 12) {
        float mxv = -1e30f;
        for (int kx = 0; kx < 12; kx++) mxv = fmaxf(mxv, S[tid][kx]);
        float smv = 0.f;
        for (int kx = 0; kx < 12; kx++) { float pv = __expf(S[tid][kx] - mxv); S[tid][kx] = pv; smv += pv; }
        float inv = 1.f / smv;
        for (int kx = 0; kx < 12; kx++) S[tid][kx] *= inv;
    }
    __syncthreads();
    float cv = 0.f;
    #pragma unroll
    for (int kx = 0; kx < 12; kx++) cv += S[t][kx] * V[kx][d];
    g_ctx[((size_t)b * 12 + t) * 96 + h * 32 + d] = cv;
}

// ---------------- K2c: TATout = LN(ctx @ fc_t + TEmx); 4 rows/block, 512 threads ----------------
__global__ void __launch_bounds__(512) k_tatout(const float* __restrict__ fct) {
    int r0 = blockIdx.x * 4;   // 48 blocks, rows bt = r0..r0+3
    int tid = threadIdx.x;
    __shared__ unsigned long long csp[4][96];
    __shared__ float red[16][8];
    __shared__ float stats[8];
    if (tid < 384) {
        int r = tid / 96, jx = tid % 96;
        float cv = g_ctx[(r0 + r) * 96 + jx];
        csp[r][jx] = pk2(cv, cv);
    }
    __syncthreads();
    const unsigned long long* fct2 = (const unsigned long long*)fct;
    const unsigned long long* Eb2 = (const unsigned long long*)g_TEmx;
    unsigned long long v0 = Eb2[(size_t)(r0 + 0) * 512 + tid];
    unsigned long long v1 = Eb2[(size_t)(r0 + 1) * 512 + tid];
    unsigned long long v2 = Eb2[(size_t)(r0 + 2) * 512 + tid];
    unsigned long long v3 = Eb2[(size_t)(r0 + 3) * 512 + tid];
    #pragma unroll 4
    for (int jx = 0; jx < 96; jx++) {
        unsigned long long f = fct2[(size_t)jx * 512 + tid];
        v0 = ffma2(csp[0][jx], f, v0);
        v1 = ffma2(csp[1][jx], f, v1);
        v2 = ffma2(csp[2][jx], f, v2);
        v3 = ffma2(csp[3][jx], f, v3);
    }
    unsigned long long vr[4] = {v0, v1, v2, v3};
    float p[8];
    #pragma unroll
    for (int r = 0; r < 4; r++) {
        float a, bv; unpk(vr[r], a, bv);
        p[2 * r] = a + bv; p[2 * r + 1] = a * a + bv * bv;
    }
    #pragma unroll
    for (int o = 16; o > 0; o >>= 1)
        #pragma unroll
        for (int i = 0; i < 8; i++) p[i] += __shfl_xor_sync(0xFFFFFFFFu, p[i], o);
    int w = tid >> 5, l = tid & 31;
    if (l == 0) {
        #pragma unroll
        for (int i = 0; i < 8; i++) red[w][i] = p[i];
    }
    __syncthreads();
    if (tid < 8) {
        float acc = 0.f;
        #pragma unroll
        for (int ww = 0; ww < 16; ww++) acc += red[ww][tid];
        stats[tid] = acc;
    }
    __syncthreads();
    unsigned long long* Tb2 = (unsigned long long*)g_TAT;
    #pragma unroll
    for (int r = 0; r < 4; r++) {
        float mu = stats[2 * r] * (1.f / 1024.f);
        float var = stats[2 * r + 1] * (1.f / 1024.f) - mu * mu;
        float rstd = rsqrtf(var + 1e-5f);
        float a, bv; unpk(vr[r], a, bv);
        Tb2[(size_t)(r0 + r) * 512 + tid] = pk2((a - mu) * rstd, (bv - mu) * rstd);
    }
}

// ---------------- K3a: pre_conv + pos_embed_S + LN over 512 -> SEmx (coalesced pcw staging) ----------------
__global__ void __launch_bounds__(256) k_semx(
        const float* __restrict__ pcw, const float* __restrict__ pcb,
        const float* __restrict__ peS, const float* __restrict__ gS,
        const float* __restrict__ bS) {
    int tid = threadIdx.x;
    int b = blockIdx.x >> 7;
    int n = ((blockIdx.x & 127) << 3) + (tid >> 5);
    int lane = tid & 31;
    // pw[t][d] = pcw[d*12 + t], staged with coalesced float4 loads
    __shared__ __align__(8) float pw[12][512];
    #pragma unroll
    for (int k = 0; k < 6; k++) {
        float4 v4 = *(const float4*)&pcw[tid * 24 + k * 4];
        float vv[4] = {v4.x, v4.y, v4.z, v4.w};
        #pragma unroll
        for (int e = 0; e < 4; e++) {
            int j = k * 4 + e;                // 0..23
            pw[j % 12][2 * tid + j / 12] = vv[e];
        }
    }
    __syncthreads();

    float tv = 0.f;
    if (lane < 12) tv = g_TAT[((size_t)b * 12 + lane) * 1024 + n];
    unsigned long long ttp[12];
    #pragma unroll
    for (int t = 0; t < 12; t++) {
        float sv = __shfl_sync(0xFFFFFFFFu, tv, t);
        ttp[t] = pk2(sv, sv);
    }
    const unsigned long long* pcb2 = (const unsigned long long*)pcb;
    const unsigned long long* peS2 = (const unsigned long long*)peS + (size_t)n * 256;
    unsigned long long v2[8];
    float s = 0.f, s2 = 0.f;
    #pragma unroll
    for (int i = 0; i < 8; i++) {
        int dp = lane + 32 * i;
        unsigned long long v = add2(pcb2[dp], peS2[dp]);
        #pragma unroll
        for (int t = 0; t < 12; t++)
            v = ffma2(ttp[t], *(const unsigned long long*)&pw[t][2 * dp], v);
        v2[i] = v;
        float a, bb; unpk(v, a, bb);
        s += a + bb; s2 += a * a + bb * bb;
    }
    #pragma unroll
    for (int o = 16; o > 0; o >>= 1) {
        s  += __shfl_xor_sync(0xFFFFFFFFu, s,  o);
        s2 += __shfl_xor_sync(0xFFFFFFFFu, s2, o);
    }
    float mu = s * (1.f / 512.f);
    float rstd = rsqrtf(s2 * (1.f / 512.f) - mu * mu + 1e-5f);
    const unsigned long long* g2  = (const unsigned long long*)gS;
    const unsigned long long* bb2 = (const unsigned long long*)bS;
    unsigned long long* o2 = (unsigned long long*)g_SEmx + ((size_t)b * 1024 + n) * 256;
    #pragma unroll
    for (int i = 0; i < 8; i++) {
        int dp = lane + 32 * i;
        float a, bbv; unpk(v2[i], a, bbv);
        float ga, gb; unpk(g2[dp], ga, gb);
        float ba, bx; unpk(bb2[dp], ba, bx);
        o2[dp] = pk2((a - mu) * rstd * ga + ba, (bbv - mu) * rstd * gb + bx);
    }
}

// ---------------- K3b: GEMM QKs = SEmx(16384x512) @ [WQ_s|WK_s](512x192) via tf32 MMA ----------------
__global__ void __launch_bounds__(256, 1) k_qks_gemm(const float* __restrict__ WQ,
                                                     const float* __restrict__ WK) {
    __shared__ __align__(16) float As[16][132];   // [k][m], tf32 bits, pad 132
    __shared__ __align__(16) float Bs[16][200];   // [k][n], tf32 bits, pad 200
    int m0 = blockIdx.x * 128;    // 128 blocks
    int tid = threadIdx.x;
    int g = tid >> 5, lane = tid & 31;
    int grp = lane >> 2, tig = lane & 3;

    float C[24][4];
    #pragma unroll
    for (int nt = 0; nt < 24; nt++)
        #pragma unroll
        for (int e = 0; e < 4; e++) C[nt][e] = 0.f;

    for (int k0 = 0; k0 < 512; k0 += 16) {
        {
            int m = tid & 127; int kh = (tid >> 7) * 8;
            const float4* src = (const float4*)&g_SEmx[((size_t)m0 + m) * 512 + k0 + kh];
            float4 a0 = src[0], a1 = src[1];
            As[kh + 0][m] = __uint_as_float(to_tf32(a0.x));
            As[kh + 1][m] = __uint_as_float(to_tf32(a0.y));
            As[kh + 2][m] = __uint_as_float(to_tf32(a0.z));
            As[kh + 3][m] = __uint_as_float(to_tf32(a0.w));
            As[kh + 4][m] = __uint_as_float(to_tf32(a1.x));
            As[kh + 5][m] = __uint_as_float(to_tf32(a1.y));
            As[kh + 6][m] = __uint_as_float(to_tf32(a1.z));
            As[kh + 7][m] = __uint_as_float(to_tf32(a1.w));
        }
        #pragma unroll
        for (int i = 0; i < 12; i++) {
            int e = tid + 256 * i; int kk2 = e / 192; int jl = e % 192;
            float v = (jl < 96) ? WQ[(k0 + kk2) * 96 + jl] : WK[(k0 + kk2) * 96 + (jl - 96)];
            Bs[kk2][jl] = __uint_as_float(to_tf32(v));
        }
        __syncthreads();
        #pragma unroll
        for (int k8 = 0; k8 < 2; k8++) {
            unsigned int A[4];
            A[0] = __float_as_uint(As[k8 * 8 + tig][g * 16 + grp]);
            A[1] = __float_as_uint(As[k8 * 8 + tig][g * 16 + grp + 8]);
            A[2] = __float_as_uint(As[k8 * 8 + tig + 4][g * 16 + grp]);
            A[3] = __float_as_uint(As[k8 * 8 + tig + 4][g * 16 + grp + 8]);
            #pragma unroll
            for (int nt = 0; nt < 24; nt++) {
                unsigned int Bf[2];
                Bf[0] = __float_as_uint(Bs[k8 * 8 + tig][nt * 8 + grp]);
                Bf[1] = __float_as_uint(Bs[k8 * 8 + tig + 4][nt * 8 + grp]);
                MMA_TF32(C[nt], A, Bf);
            }
        }
        __syncthreads();
    }
    #pragma unroll
    for (int nt = 0; nt < 24; nt++) {
        int col = nt * 8 + 2 * tig;
        size_t r0 = ((size_t)m0 + g * 16 + grp) * 192 + col;
        *(float2*)&g_QKs[r0]             = make_float2(C[nt][0], C[nt][1]);
        *(float2*)&g_QKs[r0 + 8 * 192]   = make_float2(C[nt][2], C[nt][3]);
    }
}

// ---------------- K3c: prep = {adj*cmask, cheb} pack  +  gtu weight reorder ----------------
__global__ void k_prep(const float* __restrict__ adj, const float* __restrict__ cmask,
                       const float* __restrict__ cheb,
                       const float* __restrict__ w3, const float* __restrict__ w5,
                       const float* __restrict__ w7) {
    if (blockIdx.x < 6144) {
        int idx2 = blockIdx.x * 256 + threadIdx.x;   // 1.5M threads, 2 elems each
        int idx = idx2 * 2;
        int mj = idx & 1048575;
        float2 av = *(const float2*)&adj[mj];
        float2 cm = *(const float2*)&cmask[idx];
        float2 cb = *(const float2*)&cheb[idx];
        ulonglong2 o;
        o.x = pk2(av.x * cm.x, cb.x);
        o.y = pk2(av.y * cm.y, cb.y);
        *(ulonglong2*)&g_bc[idx] = o;
    } else {
        int idx = (blockIdx.x - 6144) * 256 + threadIdx.x;
        if (idx >= 15360) return;
        int c = idx & 31; int rest = idx >> 5; int pos = rest % 15; int ci = rest / 15;
        float wa, wb;
        if (pos < 3)      { wa = w3[(c * 32 + ci) * 3 + pos];       wb = w3[((c + 32) * 32 + ci) * 3 + pos]; }
        else if (pos < 8) { wa = w5[(c * 32 + ci) * 5 + (pos - 3)]; wb = w5[((c + 32) * 32 + ci) * 5 + (pos - 3)]; }
        else              { wa = w7[(c * 32 + ci) * 7 + (pos - 8)]; wb = w7[((c + 32) * 32 + ci) * 7 + (pos - 8)]; }
        g_Wr2[(ci * 15 + pos) * 32 + c] = pk2(wa, wb);
    }
}

// ---------------- K4: spatial column-softmax attention — tf32 MMA QK + SIMT PV, 8-b loop ----------------
__global__ void __launch_bounds__(256, 2) k_spatial(const float* __restrict__ x) {
    int j0 = blockIdx.x * 32; int kk = blockIdx.y;
    int quarter = blockIdx.z & 3; int bhalf = blockIdx.z >> 2;
    int tid = threadIdx.x; int lane = tid & 31; int g = tid >> 5;
    int tig = lane & 3, grp = lane >> 2;

    __shared__ __align__(16) float xs[256][12];        // 12 KB
    __shared__ __align__(16) float pcs[8][32][34];     // 34.8 KB (pitch 34 avoids bank conflicts)
    __shared__ float r_sm[8][32];                      // 1 KB

    const float* qk = g_QKs;
    const int mbase = quarter * 256;
    const size_t kbase = (size_t)kk << 20;
    const float SCALE = 0.17677669529663687f;
    const int mw = mbase + g * 32;

    for (int bi = 0; bi < 8; bi++) {
        int b = bhalf * 8 + bi;
        const size_t brow = (size_t)b * 1024;

        // stage x quarter (256 rows x 12 t)
        {
            const unsigned long long* x2 = (const unsigned long long*)x;
            unsigned long long* xs2 = (unsigned long long*)&xs[0][0];
            #pragma unroll
            for (int i = 0; i < 6; i++)
                xs2[tid + 256 * i] = x2[(brow + mbase) * 6 + tid + 256 * i];
        }

        // B fragments: K tile (32 j) x (32 d), col-major (b0: k=tig, n=grp)
        unsigned int Bf[4][4][2];
        #pragma unroll
        for (int jt = 0; jt < 4; jt++) {
            size_t rowb = (brow + j0 + jt * 8 + grp) * 192 + 96 + kk * 32;
            #pragma unroll
            for (int ks = 0; ks < 4; ks++) {
                int d = ks * 8 + tig;
                Bf[jt][ks][0] = to_tf32(qk[rowb + d]);
                Bf[jt][ks][1] = to_tf32(qk[rowb + d + 4]);
            }
        }
        __syncthreads();   // xs ready (also orders prior-iter merge reads before pcs overwrite)

        // GEMM1: this warp's 32m x 32j S tile via 32 mma
        float C[2][4][4];
        #pragma unroll
        for (int mt = 0; mt < 2; mt++)
            #pragma unroll
            for (int jt = 0; jt < 4; jt++)
                #pragma unroll
                for (int e = 0; e < 4; e++) C[mt][jt][e] = 0.f;

        #pragma unroll
        for (int ks = 0; ks < 4; ks++) {
            #pragma unroll
            for (int mt = 0; mt < 2; mt++) {
                int m = mw + mt * 16 + grp;
                int dd = ks * 8 + tig;
                size_t r0 = (brow + m) * 192 + kk * 32 + dd;
                size_t r1 = (brow + m + 8) * 192 + kk * 32 + dd;
                unsigned int A[4];
                A[0] = to_tf32(qk[r0]);
                A[1] = to_tf32(qk[r1]);
                A[2] = to_tf32(qk[r0 + 4]);
                A[3] = to_tf32(qk[r1 + 4]);
                #pragma unroll
                for (int jt = 0; jt < 4; jt++)
                    MMA_TF32(C[mt][jt], A, Bf[jt][ks]);
            }
        }

        // elementwise: p = exp(s*scale + bias); pc = p*cheb; denominators
        // bc loads hit L1 for bi >= 1 (64 KB tile is b-invariant and L1-resident)
        float sden[4][2];
        #pragma unroll
        for (int jt = 0; jt < 4; jt++) { sden[jt][0] = 0.f; sden[jt][1] = 0.f; }

        #pragma unroll
        for (int mt = 0; mt < 2; mt++) {
            int mg0 = mw + mt * 16 + grp;
            #pragma unroll
            for (int jt = 0; jt < 4; jt++) {
                int jg = j0 + jt * 8 + 2 * tig;
                ulonglong2 bc0 = *(const ulonglong2*)&g_bc[kbase + (size_t)mg0 * 1024 + jg];
                ulonglong2 bc1 = *(const ulonglong2*)&g_bc[kbase + (size_t)(mg0 + 8) * 1024 + jg];
                float bias, cp;
                unpk(bc0.x, bias, cp);
                float p0 = __expf(C[mt][jt][0] * SCALE + bias); sden[jt][0] += p0; float pc0 = p0 * cp;
                unpk(bc0.y, bias, cp);
                float p1 = __expf(C[mt][jt][1] * SCALE + bias); sden[jt][1] += p1; float pc1 = p1 * cp;
                unpk(bc1.x, bias, cp);
                float p2 = __expf(C[mt][jt][2] * SCALE + bias); sden[jt][0] += p2; float pc2 = p2 * cp;
                unpk(bc1.y, bias, cp);
                float p3 = __expf(C[mt][jt][3] * SCALE + bias); sden[jt][1] += p3; float pc3 = p3 * cp;
                int ml = mt * 16 + grp;
                int jl = jt * 8 + 2 * tig;
                *(float2*)&pcs[g][ml][jl]     = make_float2(pc0, pc1);
                *(float2*)&pcs[g][ml + 8][jl] = make_float2(pc2, pc3);
            }
        }

        // reduce denominators over grp (threads sharing same tig)
        #pragma unroll
        for (int jt = 0; jt < 4; jt++)
            #pragma unroll
            for (int cc = 0; cc < 2; cc++) {
                float v = sden[jt][cc];
                v += __shfl_xor_sync(0xFFFFFFFFu, v, 4);
                v += __shfl_xor_sync(0xFFFFFFFFu, v, 8);
                v += __shfl_xor_sync(0xFFFFFFFFu, v, 16);
                sden[jt][cc] = v;
            }
        if (grp == 0) {
            #pragma unroll
            for (int jt = 0; jt < 4; jt++) {
                r_sm[g][jt * 8 + 2 * tig]     = sden[jt][0];
                r_sm[g][jt * 8 + 2 * tig + 1] = sden[jt][1];
            }
        }
        __syncwarp();

        // PV: lane = j, accumulate over this warp's 32 m
        unsigned long long acc[6];
        #pragma unroll
        for (int i = 0; i < 6; i++) acc[i] = 0ull;
        #pragma unroll 4
        for (int m = 0; m < 32; m++) {
            float pcv = pcs[g][m][lane];
            unsigned long long wp = pk2(pcv, pcv);
            const unsigned long long* xr = (const unsigned long long*)&xs[g * 32 + m][0];
            #pragma unroll
            for (int i = 0; i < 6; i++) acc[i] = ffma2(wp, xr[i], acc[i]);
        }

        // merge 8 warp-partials (reuse pcs region for r_acc AFTER all PV done)
        __syncthreads();
        unsigned long long* r_acc = (unsigned long long*)&pcs[0][0][0];   // [8*32][6]
        #pragma unroll
        for (int i = 0; i < 6; i++) r_acc[(g * 32 + lane) * 6 + i] = acc[i];
        __syncthreads();
        if (g == 0) {
            float S = 0.f;
            unsigned long long o[6];
            #pragma unroll
            for (int i = 0; i < 6; i++) o[i] = 0ull;
            #pragma unroll
            for (int q = 0; q < 8; q++) {
                S += r_sm[q][lane];
                #pragma unroll
                for (int i = 0; i < 6; i++) o[i] = add2(o[i], r_acc[(q * 32 + lane) * 6 + i]);
            }
            int jidx = ((b * 3 + kk) << 10) + j0 + lane;
            unsigned long long* pp = g_part + (size_t)quarter * 7 * 49152;
            #pragma unroll
            for (int i = 0; i < 6; i++) pp[i * 49152 + jidx] = o[i];
            pp[6 * 49152 + jidx] = pk2(S, S);
        }
        // next iteration's first __syncthreads orders g0's r_acc reads
        // before pcs is overwritten.
    }
}

// ---------------- K6: merge quarters + Theta contraction + GTUs + fcmy + residual + final LN ----------------
__global__ void __launch_bounds__(256, 2) k_gtu(
    const float* __restrict__ x, const float* __restrict__ Theta,
    const float* __restrict__ b3, const float* __restrict__ b5, const float* __restrict__ b7,
    const float* __restrict__ rcw, const float* __restrict__ rcb,
    const float* __restrict__ fcw, const float* __restrict__ fcb,
    const float* __restrict__ gf, const float* __restrict__ bfin,
    float* __restrict__ out) {
    int n0 = blockIdx.x * 8; int b = blockIdx.y;
    int tid = threadIdx.x; int c = tid & 31; int p = tid >> 5; int n = n0 + p;
    __shared__ unsigned long long Xp[8][32][12];
    __shared__ float Vs[8][32][12];
    __shared__ float rhs_s[8][3][12];
    __shared__ unsigned long long fcw2[24][6];

    if (tid < 144) {
        int w = tid / 6, t2 = tid % 6;
        fcw2[w][t2] = pk2(fcw[w * 12 + 2 * t2], fcw[w * 12 + 2 * t2 + 1]);
    }

    // merge the four m-quarter partials for this block's 8 n-rows (was k_smerge)
    if (tid < 144) {
        int e = tid;                       // n_l(8) x kk(3) x i(6)
        int n_l = e / 18; int r = e % 18; int kk = r / 6; int i = r % 6;
        int jidx = ((b * 3 + kk) << 10) + n0 + n_l;
        unsigned long long o = 0ull;
        float S = 0.f;
        #pragma unroll
        for (int q = 0; q < 4; q++) {
            const unsigned long long* pp = g_part + (size_t)q * 7 * 49152;
            o = add2(o, pp[i * 49152 + jidx]);
            float sl, sh; unpk(pp[6 * 49152 + jidx], sl, sh);
            S += sl;
        }
        float inv = 1.f / S;
        float a, bv; unpk(o, a, bv);
        rhs_s[n_l][kk][2 * i]     = a * inv;
        rhs_s[n_l][kk][2 * i + 1] = bv * inv;
    }
    __syncthreads();

    {
        float th0 = Theta[c], th1 = Theta[32 + c], th2 = Theta[64 + c];
        #pragma unroll
        for (int t = 0; t < 12; t++) {
            float v = rhs_s[p][0][t] * th0 + rhs_s[p][1][t] * th1 + rhs_s[p][2][t] * th2;
            v = fmaxf(v, 0.f);
            Xp[p][c][t] = pk2(v, v);
        }
    }
    __syncthreads();

    // v2 accumulates fcmy across both passes
    unsigned long long v2[6];
    {
        const unsigned long long* fcb2 = (const unsigned long long*)fcb;
        #pragma unroll
        for (int t2 = 0; t2 < 6; t2++) v2[t2] = fcb2[t2];
    }

    // ---- pass 1: gtu3 (w 0..9) + gtu7 (w 18..23), 16 accumulators ----
    {
        unsigned long long yA[16];
        unsigned long long i3 = pk2(b3[c], b3[c + 32]);
        unsigned long long i7 = pk2(b7[c], b7[c + 32]);
        #pragma unroll
        for (int w = 0; w < 10; w++) yA[w] = i3;
        #pragma unroll
        for (int w = 0; w < 6; w++)  yA[10 + w] = i7;

        for (int ci = 0; ci < 32; ci++) {
            unsigned long long Xr[12];
            #pragma unroll
            for (int t = 0; t < 12; t++) Xr[t] = Xp[p][ci][t];
            const unsigned long long* wr = g_Wr2 + (size_t)ci * 15 * 32 + c;
            #pragma unroll
            for (int dt = 0; dt < 3; dt++) {
                unsigned long long wv = __ldg(&wr[dt * 32]);
                #pragma unroll
                for (int w = 0; w < 10; w++) yA[w] = ffma2(Xr[w + dt], wv, yA[w]);
            }
            #pragma unroll
            for (int dt = 0; dt < 7; dt++) {
                unsigned long long wv = __ldg(&wr[(8 + dt) * 32]);
                #pragma unroll
                for (int w = 0; w < 6; w++) yA[10 + w] = ffma2(Xr[w + dt], wv, yA[10 + w]);
            }
        }
        #pragma unroll
        for (int w = 0; w < 16; w++) {
            float ya, yb; unpk(yA[w], ya, yb);
            float tv = 1.f - 2.f / (__expf(2.f * ya) + 1.f);
            float sg = 1.f / (1.f + __expf(-yb));
            float gv = tv * sg;
            unsigned long long gp = pk2(gv, gv);
            int row = (w < 10) ? w : (8 + w);   // w 10..15 -> rows 18..23
            #pragma unroll
            for (int t2 = 0; t2 < 6; t2++) v2[t2] = ffma2(gp, fcw2[row][t2], v2[t2]);
        }
    }

    // ---- pass 2: gtu5 (w 10..17), 8 accumulators ----
    {
        unsigned long long yB[8];
        unsigned long long i5 = pk2(b5[c], b5[c + 32]);
        #pragma unroll
        for (int w = 0; w < 8; w++) yB[w] = i5;

        for (int ci = 0; ci < 32; ci++) {
            unsigned long long Xr[12];
            #pragma unroll
            for (int t = 0; t < 12; t++) Xr[t] = Xp[p][ci][t];
            const unsigned long long* wr = g_Wr2 + (size_t)ci * 15 * 32 + c;
            #pragma unroll
            for (int dt = 0; dt < 5; dt++) {
                unsigned long long wv = __ldg(&wr[(3 + dt) * 32]);
                #pragma unroll
                for (int w = 0; w < 8; w++) yB[w] = ffma2(Xr[w + dt], wv, yB[w]);
            }
        }
        #pragma unroll
        for (int w = 0; w < 8; w++) {
            float ya, yb; unpk(yB[w], ya, yb);
            float tv = 1.f - 2.f / (__expf(2.f * ya) + 1.f);
            float sg = 1.f / (1.f + __expf(-yb));
            float gv = tv * sg;
            unsigned long long gp = pk2(gv, gv);
            #pragma unroll
            for (int t2 = 0; t2 < 6; t2++) v2[t2] = ffma2(gp, fcw2[10 + w][t2], v2[t2]);
        }
    }

    float rw = rcw[c], rb = rcb[c];
    const unsigned long long* xp2 = (const unsigned long long*)x + ((size_t)b * 1024 + n) * 6;
    #pragma unroll
    for (int t2 = 0; t2 < 6; t2++) {
        float va, vb; unpk(v2[t2], va, vb);
        float xa, xb; unpk(xp2[t2], xa, xb);
        va = fmaxf(va, 0.f); vb = fmaxf(vb, 0.f);
        Vs[p][c][2 * t2]     = fmaxf(xa * rw + rb + va, 0.f);
        Vs[p][c][2 * t2 + 1] = fmaxf(xb * rw + rb + vb, 0.f);
    }
    __syncthreads();

    if (tid < 96) {
        int p2 = tid / 12, t2 = tid % 12;
        float s = 0.f, s2 = 0.f;
        #pragma unroll
        for (int cc = 0; cc < 32; cc++) { float v = Vs[p2][cc][t2]; s += v; s2 += v * v; }
        float mu = s * (1.f / 32.f);
        float var = s2 * (1.f / 32.f) - mu * mu;
        float rstd = rsqrtf(var + 1e-5f);
        float* op = out + (((size_t)b * 1024 + n0 + p2) * 32) * 12 + t2;
        #pragma unroll
        for (int cc = 0; cc < 32; cc++)
            op[cc * 12] = (Vs[p2][cc][t2] - mu) * rstd * gf[cc] + bfin[cc];
    }
}

// ---------------- launch ----------------
extern "C" void kernel_launch(void* const* d_in, const int* in_sizes, int n_in,
                              void* d_out, int out_size) {
    const float* x     = (const float*)d_in[0];
    const float* resa  = (const float*)d_in[1];
    const float* peT   = (const float*)d_in[2];
    const float* gT    = (const float*)d_in[3];
    const float* bT    = (const float*)d_in[4];
    const float* WQt   = (const float*)d_in[5];
    const float* WKt   = (const float*)d_in[6];
    const float* WVt   = (const float*)d_in[7];
    const float* fct   = (const float*)d_in[8];
    const float* pcw   = (const float*)d_in[9];
    const float* pcb   = (const float*)d_in[10];
    const float* peS   = (const float*)d_in[11];
    const float* gS    = (const float*)d_in[12];
    const float* bS    = (const float*)d_in[13];
    const float* WQs   = (const float*)d_in[14];
    const float* WKs   = (const float*)d_in[15];
    const float* cheb  = (const float*)d_in[16];
    const float* adj   = (const float*)d_in[17];
    const float* cmask = (const float*)d_in[18];
    const float* Theta = (const float*)d_in[19];
    const float* w3    = (const float*)d_in[20];
    const float* b3    = (const float*)d_in[21];
    const float* w5    = (const float*)d_in[22];
    const float* b5    = (const float*)d_in[23];
    const float* w7    = (const float*)d_in[24];
    const float* b7    = (const float*)d_in[25];
    const float* rcw   = (const float*)d_in[26];
    const float* rcb   = (const float*)d_in[27];
    const float* fcw   = (const float*)d_in[28];
    const float* fcb   = (const float*)d_in[29];
    const float* gf    = (const float*)d_in[30];
    const float* bf    = (const float*)d_in[31];

    float* out  = (float*)d_out;
    float* reat = out + (size_t)16 * 1024 * 32 * 12;  // re_At after main output

    k_temporal_ln<<<16, 1024>>>(x, peT, gT, bT);
    k_qkv<<<dim3(16, 4), 288>>>(WQt, WKt, WVt);
    k_tattn<<<48, 384>>>(resa, reat);
    k_tatout<<<48, 512>>>(fct);
    k_prep<<<6204, 256>>>(adj, cmask, cheb, w3, w5, w7);
    k_semx<<<2048, 256>>>(pcw, pcb, peS, gS, bS);
    k_qks_gemm<<<128, 256>>>(WQs, WKs);
    k_spatial<<<dim3(32, 3, 8), 256>>>(x);
    k_gtu<<<dim3(128, 16), 256>>>(x, Theta, b3, b5, b7, rcw, rcb, fcw, fcb, gf, bf, out);
}

// round 17
// speedup vs baseline: 1.0688x; 1.0688x over previous
#include <cuda_runtime.h>
#include <cuda_bf16.h>
#include <cstdint>
#include <math.h>

// ---------------- constants ----------------
// B=16, N=1024, T=12, F=1, D_MODEL=512, D_K=D_V=32, H=3, K=3, C=32

// ---------------- scratch (static device memory; no allocation) ----------------
__device__ float g_TEmx[16 * 12 * 1024];      // (B,T,N)
__device__ float g_qkvp[4 * 16 * 12 * 288];   // partial QKV per n-quarter
__device__ float g_ctx [16 * 12 * 96];        // (B,T,96)
__device__ float g_TAT [16 * 12 * 1024];      // (B,T,N)
__device__ float g_SEmx[16 * 1024 * 512];     // (B,N,512)
__device__ float g_QKs [16 * 1024 * 192];     // (B,N,192): 0..95 = Qs, 96..191 = Ks
__device__ float g_rhs [16 * 3 * 1024 * 12];  // (B,K,N,T)
__device__ unsigned long long g_Wr2[32 * 15 * 32];    // {wa,wb} per (ci,pos,c)
__device__ unsigned long long g_bc [3 * 1024 * 1024]; // {adj*cmask, cheb} per (k,m,j)
__device__ unsigned long long g_part[4 * 7 * 49152];  // spatial partials [quarter][slot][jidx]

// ---------------- f32x2 helpers ----------------
__device__ __forceinline__ unsigned long long pk2(float a, float b) {
    unsigned long long r; asm("mov.b64 %0, {%1,%2};" : "=l"(r) : "f"(a), "f"(b)); return r;
}
__device__ __forceinline__ void unpk(unsigned long long v, float& a, float& b) {
    asm("mov.b64 {%0,%1}, %2;" : "=f"(a), "=f"(b) : "l"(v));
}
__device__ __forceinline__ unsigned long long ffma2(unsigned long long a, unsigned long long b, unsigned long long c) {
    unsigned long long d; asm("fma.rn.f32x2 %0, %1, %2, %3;" : "=l"(d) : "l"(a), "l"(b), "l"(c)); return d;
}
__device__ __forceinline__ unsigned long long mul2(unsigned long long a, unsigned long long b) {
    unsigned long long d; asm("mul.rn.f32x2 %0, %1, %2;" : "=l"(d) : "l"(a), "l"(b)); return d;
}
__device__ __forceinline__ unsigned long long add2(unsigned long long a, unsigned long long b) {
    unsigned long long d; asm("add.rn.f32x2 %0, %1, %2;" : "=l"(d) : "l"(a), "l"(b)); return d;
}
__device__ __forceinline__ unsigned int to_tf32(float f) {
    unsigned int r; asm("cvt.rna.tf32.f32 %0, %1;" : "=r"(r) : "f"(f)); return r;
}
#define MMA_TF32(c, A, B)                                                      \
    asm volatile("mma.sync.aligned.m16n8k8.row.col.f32.tf32.tf32.f32 "         \
        "{%0,%1,%2,%3}, {%4,%5,%6,%7}, {%8,%9}, {%0,%1,%2,%3};"                \
        : "+f"((c)[0]), "+f"((c)[1]), "+f"((c)[2]), "+f"((c)[3])               \
        : "r"((A)[0]), "r"((A)[1]), "r"((A)[2]), "r"((A)[3]),                  \
          "r"((B)[0]), "r"((B)[1]))

// ---------------- helpers ----------------
__device__ __forceinline__ void block_reduce2(float& s, float& s2, float* shm) {
    #pragma unroll
    for (int o = 16; o > 0; o >>= 1) {
        s  += __shfl_down_sync(0xFFFFFFFFu, s,  o);
        s2 += __shfl_down_sync(0xFFFFFFFFu, s2, o);
    }
    int nw = blockDim.x >> 5;
    int w = threadIdx.x >> 5, l = threadIdx.x & 31;
    if (l == 0) { shm[w] = s; shm[w + 32] = s2; }
    __syncthreads();
    if (w == 0) {
        s  = (l < nw) ? shm[l] : 0.f;
        s2 = (l < nw) ? shm[l + 32] : 0.f;
        #pragma unroll
        for (int o = 16; o > 0; o >>= 1) {
            s  += __shfl_down_sync(0xFFFFFFFFu, s,  o);
            s2 += __shfl_down_sync(0xFFFFFFFFu, s2, o);
        }
        if (l == 0) { shm[0] = s; shm[1] = s2; }
    }
    __syncthreads();
    s = shm[0]; s2 = shm[1];
}

// ---------------- K1: temporal embed + LN over N (all-coalesced; thread = n) ----------------
__global__ void __launch_bounds__(1024) k_temporal_ln(
        const float* __restrict__ x, const float* __restrict__ peT,
        const float* __restrict__ gT, const float* __restrict__ bT) {
    int b = blockIdx.x;            // 16 blocks
    int n = threadIdx.x;           // 1024 threads
    __shared__ float red[32][24];
    __shared__ float stats[24];

    float v[12];
    {
        const float4* xr = (const float4*)(x + ((size_t)b * 1024 + n) * 12);
        float4 x0 = xr[0], x1 = xr[1], x2 = xr[2];
        v[0]=x0.x; v[1]=x0.y; v[2]=x0.z; v[3]=x0.w;
        v[4]=x1.x; v[5]=x1.y; v[6]=x1.z; v[7]=x1.w;
        v[8]=x2.x; v[9]=x2.y; v[10]=x2.z; v[11]=x2.w;
    }
    #pragma unroll
    for (int t = 0; t < 12; t++) v[t] += peT[t * 1024 + n];

    float pv[12], qv[12];
    #pragma unroll
    for (int t = 0; t < 12; t++) { pv[t] = v[t]; qv[t] = v[t] * v[t]; }
    #pragma unroll
    for (int o = 16; o > 0; o >>= 1) {
        #pragma unroll
        for (int t = 0; t < 12; t++) {
            pv[t] += __shfl_xor_sync(0xFFFFFFFFu, pv[t], o);
            qv[t] += __shfl_xor_sync(0xFFFFFFFFu, qv[t], o);
        }
    }
    int w = threadIdx.x >> 5, l = threadIdx.x & 31;
    if (l == 0) {
        #pragma unroll
        for (int t = 0; t < 12; t++) { red[w][t] = pv[t]; red[w][12 + t] = qv[t]; }
    }
    __syncthreads();
    if (threadIdx.x < 24) {
        float acc = 0.f;
        #pragma unroll
        for (int ww = 0; ww < 32; ww++) acc += red[ww][threadIdx.x];
        stats[threadIdx.x] = acc;
    }
    __syncthreads();

    float gn = gT[n], bn = bT[n];
    #pragma unroll
    for (int t = 0; t < 12; t++) {
        float mu = stats[t] * (1.f / 1024.f);
        float var = stats[12 + t] * (1.f / 1024.f) - mu * mu;
        float rstd = rsqrtf(var + 1e-5f);
        g_TEmx[((size_t)b * 12 + t) * 1024 + n] = (v[t] - mu) * rstd * gn + bn;
    }
}

// ---------------- K2a: QKV projection partials; grid (16 b, 4 quarters), 288 thr ----------------
__global__ void k_qkv(const float* __restrict__ WQ, const float* __restrict__ WK,
                      const float* __restrict__ WV) {
    int b = blockIdx.x; int q = blockIdx.y;
    int tid = threadIdx.x;
    int n0 = q * 256;
    __shared__ unsigned long long Ep[6][256];   // pairs (2tp, 2tp+1)
    for (int i = tid; i < 1536; i += 288) {
        int tp = i >> 8; int nn = i & 255;
        float a = g_TEmx[((size_t)b * 12 + 2 * tp) * 1024 + n0 + nn];
        float c = g_TEmx[((size_t)b * 12 + 2 * tp + 1) * 1024 + n0 + nn];
        Ep[tp][nn] = pk2(a, c);
    }
    __syncthreads();
    const float* W; int cw;
    if (tid < 96)       { W = WQ; cw = tid; }
    else if (tid < 192) { W = WK; cw = tid - 96; }
    else                { W = WV; cw = tid - 192; }
    unsigned long long acc[6];
    #pragma unroll
    for (int i = 0; i < 6; i++) acc[i] = 0ull;
    #pragma unroll 4
    for (int nn = 0; nn < 256; nn++) {
        float wv = W[(n0 + nn) * 96 + cw];
        unsigned long long wp = pk2(wv, wv);
        #pragma unroll
        for (int tp = 0; tp < 6; tp++) acc[tp] = ffma2(Ep[tp][nn], wp, acc[tp]);
    }
    int qb = q * 55296 + b * 12 * 288;
    #pragma unroll
    for (int tp = 0; tp < 6; tp++) {
        float lo, hi; unpk(acc[tp], lo, hi);
        g_qkvp[qb + (2 * tp) * 288 + tid]     = lo;
        g_qkvp[qb + (2 * tp + 1) * 288 + tid] = hi;
    }
}

// ---------------- K2b: temporal attention per (b,h); sums quarter-partials; writes re_At ----------------
__global__ void k_tattn(const float* __restrict__ resa, float* __restrict__ reat) {
    int b = blockIdx.x / 3, h = blockIdx.x % 3;
    int tid = threadIdx.x;
    int t = tid >> 5, d = tid & 31;   // 384 threads = 12 warps x 32
    __shared__ float Q[12][32], Kt[12][32], V[12][32], S[12][12];

    int off = b * 3456 + t * 288 + h * 32 + d;
    Q [t][d] = g_qkvp[off]       + g_qkvp[off + 55296]       + g_qkvp[off + 110592]       + g_qkvp[off + 165888];
    Kt[t][d] = g_qkvp[off + 96]  + g_qkvp[off + 96 + 55296]  + g_qkvp[off + 96 + 110592]  + g_qkvp[off + 96 + 165888];
    V [t][d] = g_qkvp[off + 192] + g_qkvp[off + 192 + 55296] + g_qkvp[off + 192 + 110592] + g_qkvp[off + 192 + 165888];
    __syncthreads();

    if (tid < 144) {
        int qi = tid / 12, ki = tid % 12;
        float s = 0.f;
        #pragma unroll
        for (int dd = 0; dd < 32; dd++) s += Q[qi][dd] * Kt[ki][dd];
        s = s * 0.17677669529663687f + resa[((size_t)(b * 3 + h) * 12 + qi) * 12 + ki];
        S[qi][ki] = s;
        reat[((size_t)(b * 3 + h) * 12 + qi) * 12 + ki] = s;
    }
    __syncthreads();
    if (tid < 12) {
        float mxv = -1e30f;
        for (int kx = 0; kx < 12; kx++) mxv = fmaxf(mxv, S[tid][kx]);
        float smv = 0.f;
        for (int kx = 0; kx < 12; kx++) { float pv = __expf(S[tid][kx] - mxv); S[tid][kx] = pv; smv += pv; }
        float inv = 1.f / smv;
        for (int kx = 0; kx < 12; kx++) S[tid][kx] *= inv;
    }
    __syncthreads();
    float cv = 0.f;
    #pragma unroll
    for (int kx = 0; kx < 12; kx++) cv += S[t][kx] * V[kx][d];
    g_ctx[((size_t)b * 12 + t) * 96 + h * 32 + d] = cv;
}

// ---------------- K2c: TATout = LN(ctx @ fc_t + TEmx); 2 rows/block, 96 blocks ----------------
__global__ void __launch_bounds__(512) k_tatout(const float* __restrict__ fct) {
    int r0 = blockIdx.x * 2;   // 96 blocks, rows bt = r0..r0+1
    int tid = threadIdx.x;
    __shared__ unsigned long long csp[2][96];
    __shared__ float red[16][4];
    __shared__ float stats[4];
    if (tid < 192) {
        int r = tid / 96, jx = tid % 96;
        float cv = g_ctx[(r0 + r) * 96 + jx];
        csp[r][jx] = pk2(cv, cv);
    }
    __syncthreads();
    const unsigned long long* fct2 = (const unsigned long long*)fct;
    const unsigned long long* Eb2 = (const unsigned long long*)g_TEmx;
    unsigned long long v0 = Eb2[(size_t)(r0 + 0) * 512 + tid];
    unsigned long long v1 = Eb2[(size_t)(r0 + 1) * 512 + tid];
    #pragma unroll 8
    for (int jx = 0; jx < 96; jx++) {
        unsigned long long f = fct2[(size_t)jx * 512 + tid];
        v0 = ffma2(csp[0][jx], f, v0);
        v1 = ffma2(csp[1][jx], f, v1);
    }
    unsigned long long vr[2] = {v0, v1};
    float p[4];
    #pragma unroll
    for (int r = 0; r < 2; r++) {
        float a, bv; unpk(vr[r], a, bv);
        p[2 * r] = a + bv; p[2 * r + 1] = a * a + bv * bv;
    }
    #pragma unroll
    for (int o = 16; o > 0; o >>= 1)
        #pragma unroll
        for (int i = 0; i < 4; i++) p[i] += __shfl_xor_sync(0xFFFFFFFFu, p[i], o);
    int w = tid >> 5, l = tid & 31;
    if (l == 0) {
        #pragma unroll
        for (int i = 0; i < 4; i++) red[w][i] = p[i];
    }
    __syncthreads();
    if (tid < 4) {
        float acc = 0.f;
        #pragma unroll
        for (int ww = 0; ww < 16; ww++) acc += red[ww][tid];
        stats[tid] = acc;
    }
    __syncthreads();
    unsigned long long* Tb2 = (unsigned long long*)g_TAT;
    #pragma unroll
    for (int r = 0; r < 2; r++) {
        float mu = stats[2 * r] * (1.f / 1024.f);
        float var = stats[2 * r + 1] * (1.f / 1024.f) - mu * mu;
        float rstd = rsqrtf(var + 1e-5f);
        float a, bv; unpk(vr[r], a, bv);
        Tb2[(size_t)(r0 + r) * 512 + tid] = pk2((a - mu) * rstd, (bv - mu) * rstd);
    }
}

// ---------------- K3a: pre_conv + pos_embed_S + LN over 512 -> SEmx (coalesced pcw staging) ----------------
__global__ void __launch_bounds__(256) k_semx(
        const float* __restrict__ pcw, const float* __restrict__ pcb,
        const float* __restrict__ peS, const float* __restrict__ gS,
        const float* __restrict__ bS) {
    int tid = threadIdx.x;
    int b = blockIdx.x >> 7;
    int n = ((blockIdx.x & 127) << 3) + (tid >> 5);
    int lane = tid & 31;
    // pw[t][d] = pcw[d*12 + t], staged with coalesced float4 loads
    __shared__ __align__(8) float pw[12][512];
    #pragma unroll
    for (int k = 0; k < 6; k++) {
        float4 v4 = *(const float4*)&pcw[tid * 24 + k * 4];
        float vv[4] = {v4.x, v4.y, v4.z, v4.w};
        #pragma unroll
        for (int e = 0; e < 4; e++) {
            int j = k * 4 + e;                // 0..23
            pw[j % 12][2 * tid + j / 12] = vv[e];
        }
    }
    __syncthreads();

    float tv = 0.f;
    if (lane < 12) tv = g_TAT[((size_t)b * 12 + lane) * 1024 + n];
    unsigned long long ttp[12];
    #pragma unroll
    for (int t = 0; t < 12; t++) {
        float sv = __shfl_sync(0xFFFFFFFFu, tv, t);
        ttp[t] = pk2(sv, sv);
    }
    const unsigned long long* pcb2 = (const unsigned long long*)pcb;
    const unsigned long long* peS2 = (const unsigned long long*)peS + (size_t)n * 256;
    unsigned long long v2[8];
    float s = 0.f, s2 = 0.f;
    #pragma unroll
    for (int i = 0; i < 8; i++) {
        int dp = lane + 32 * i;
        unsigned long long v = add2(pcb2[dp], peS2[dp]);
        #pragma unroll
        for (int t = 0; t < 12; t++)
            v = ffma2(ttp[t], *(const unsigned long long*)&pw[t][2 * dp], v);
        v2[i] = v;
        float a, bb; unpk(v, a, bb);
        s += a + bb; s2 += a * a + bb * bb;
    }
    #pragma unroll
    for (int o = 16; o > 0; o >>= 1) {
        s  += __shfl_xor_sync(0xFFFFFFFFu, s,  o);
        s2 += __shfl_xor_sync(0xFFFFFFFFu, s2, o);
    }
    float mu = s * (1.f / 512.f);
    float rstd = rsqrtf(s2 * (1.f / 512.f) - mu * mu + 1e-5f);
    const unsigned long long* g2  = (const unsigned long long*)gS;
    const unsigned long long* bb2 = (const unsigned long long*)bS;
    unsigned long long* o2 = (unsigned long long*)g_SEmx + ((size_t)b * 1024 + n) * 256;
    #pragma unroll
    for (int i = 0; i < 8; i++) {
        int dp = lane + 32 * i;
        float a, bbv; unpk(v2[i], a, bbv);
        float ga, gb; unpk(g2[dp], ga, gb);
        float ba, bx; unpk(bb2[dp], ba, bx);
        o2[dp] = pk2((a - mu) * rstd * ga + ba, (bbv - mu) * rstd * gb + bx);
    }
}

// ---------------- K3b: GEMM QKs = SEmx(16384x512) @ [WQ_s|WK_s](512x192) via tf32 MMA ----------------
__global__ void __launch_bounds__(256, 1) k_qks_gemm(const float* __restrict__ WQ,
                                                     const float* __restrict__ WK) {
    __shared__ __align__(16) float As[16][132];   // [k][m], tf32 bits, pad 132
    __shared__ __align__(16) float Bs[16][200];   // [k][n], tf32 bits, pad 200
    int m0 = blockIdx.x * 128;    // 128 blocks
    int tid = threadIdx.x;
    int g = tid >> 5, lane = tid & 31;
    int grp = lane >> 2, tig = lane & 3;

    float C[24][4];
    #pragma unroll
    for (int nt = 0; nt < 24; nt++)
        #pragma unroll
        for (int e = 0; e < 4; e++) C[nt][e] = 0.f;

    for (int k0 = 0; k0 < 512; k0 += 16) {
        {
            int m = tid & 127; int kh = (tid >> 7) * 8;
            const float4* src = (const float4*)&g_SEmx[((size_t)m0 + m) * 512 + k0 + kh];
            float4 a0 = src[0], a1 = src[1];
            As[kh + 0][m] = __uint_as_float(to_tf32(a0.x));
            As[kh + 1][m] = __uint_as_float(to_tf32(a0.y));
            As[kh + 2][m] = __uint_as_float(to_tf32(a0.z));
            As[kh + 3][m] = __uint_as_float(to_tf32(a0.w));
            As[kh + 4][m] = __uint_as_float(to_tf32(a1.x));
            As[kh + 5][m] = __uint_as_float(to_tf32(a1.y));
            As[kh + 6][m] = __uint_as_float(to_tf32(a1.z));
            As[kh + 7][m] = __uint_as_float(to_tf32(a1.w));
        }
        #pragma unroll
        for (int i = 0; i < 12; i++) {
            int e = tid + 256 * i; int kk2 = e / 192; int jl = e % 192;
            float v = (jl < 96) ? WQ[(k0 + kk2) * 96 + jl] : WK[(k0 + kk2) * 96 + (jl - 96)];
            Bs[kk2][jl] = __uint_as_float(to_tf32(v));
        }
        __syncthreads();
        #pragma unroll
        for (int k8 = 0; k8 < 2; k8++) {
            unsigned int A[4];
            A[0] = __float_as_uint(As[k8 * 8 + tig][g * 16 + grp]);
            A[1] = __float_as_uint(As[k8 * 8 + tig][g * 16 + grp + 8]);
            A[2] = __float_as_uint(As[k8 * 8 + tig + 4][g * 16 + grp]);
            A[3] = __float_as_uint(As[k8 * 8 + tig + 4][g * 16 + grp + 8]);
            #pragma unroll
            for (int nt = 0; nt < 24; nt++) {
                unsigned int Bf[2];
                Bf[0] = __float_as_uint(Bs[k8 * 8 + tig][nt * 8 + grp]);
                Bf[1] = __float_as_uint(Bs[k8 * 8 + tig + 4][nt * 8 + grp]);
                MMA_TF32(C[nt], A, Bf);
            }
        }
        __syncthreads();
    }
    #pragma unroll
    for (int nt = 0; nt < 24; nt++) {
        int col = nt * 8 + 2 * tig;
        size_t r0 = ((size_t)m0 + g * 16 + grp) * 192 + col;
        *(float2*)&g_QKs[r0]             = make_float2(C[nt][0], C[nt][1]);
        *(float2*)&g_QKs[r0 + 8 * 192]   = make_float2(C[nt][2], C[nt][3]);
    }
}

// ---------------- K3c: prep = {adj*cmask, cheb} pack  +  gtu weight reorder ----------------
__global__ void k_prep(const float* __restrict__ adj, const float* __restrict__ cmask,
                       const float* __restrict__ cheb,
                       const float* __restrict__ w3, const float* __restrict__ w5,
                       const float* __restrict__ w7) {
    if (blockIdx.x < 6144) {
        int idx2 = blockIdx.x * 256 + threadIdx.x;   // 1.5M threads, 2 elems each
        int idx = idx2 * 2;
        int mj = idx & 1048575;
        float2 av = *(const float2*)&adj[mj];
        float2 cm = *(const float2*)&cmask[idx];
        float2 cb = *(const float2*)&cheb[idx];
        ulonglong2 o;
        o.x = pk2(av.x * cm.x, cb.x);
        o.y = pk2(av.y * cm.y, cb.y);
        *(ulonglong2*)&g_bc[idx] = o;
    } else {
        int idx = (blockIdx.x - 6144) * 256 + threadIdx.x;
        if (idx >= 15360) return;
        int c = idx & 31; int rest = idx >> 5; int pos = rest % 15; int ci = rest / 15;
        float wa, wb;
        if (pos < 3)      { wa = w3[(c * 32 + ci) * 3 + pos];       wb = w3[((c + 32) * 32 + ci) * 3 + pos]; }
        else if (pos < 8) { wa = w5[(c * 32 + ci) * 5 + (pos - 3)]; wb = w5[((c + 32) * 32 + ci) * 5 + (pos - 3)]; }
        else              { wa = w7[(c * 32 + ci) * 7 + (pos - 8)]; wb = w7[((c + 32) * 32 + ci) * 7 + (pos - 8)]; }
        g_Wr2[(ci * 15 + pos) * 32 + c] = pk2(wa, wb);
    }
}

// ---------------- K4: spatial column-softmax attention — tf32 MMA QK + SIMT PV ----------------
__global__ void __launch_bounds__(256, 2) k_spatial(const float* __restrict__ x) {
    int j0 = blockIdx.x * 32; int kk = blockIdx.y;
    int b = blockIdx.z >> 2; int quarter = blockIdx.z & 3;
    int tid = threadIdx.x; int lane = tid & 31; int g = tid >> 5;
    int tig = lane & 3, grp = lane >> 2;

    __shared__ __align__(16) float xs[256][12];        // 12 KB
    __shared__ __align__(16) float pcs[8][32][34];     // 34.8 KB (pitch 34 avoids bank conflicts)
    __shared__ float r_sm[8][32];                      // 1 KB

    const float* qk = g_QKs;
    const int mbase = quarter * 256;
    const size_t brow = (size_t)b * 1024;
    const size_t kbase = (size_t)kk << 20;
    const float SCALE = 0.17677669529663687f;

    // stage x quarter (256 rows x 12 t)
    {
        const unsigned long long* x2 = (const unsigned long long*)x;
        unsigned long long* xs2 = (unsigned long long*)&xs[0][0];
        #pragma unroll
        for (int i = 0; i < 6; i++)
            xs2[tid + 256 * i] = x2[(brow + mbase) * 6 + tid + 256 * i];
    }

    // B fragments: K tile (32 j) x (32 d), col-major (b0: k=tig, n=grp)
    unsigned int Bf[4][4][2];
    #pragma unroll
    for (int jt = 0; jt < 4; jt++) {
        size_t rowb = (brow + j0 + jt * 8 + grp) * 192 + 96 + kk * 32;
        #pragma unroll
        for (int ks = 0; ks < 4; ks++) {
            int d = ks * 8 + tig;
            Bf[jt][ks][0] = to_tf32(qk[rowb + d]);
            Bf[jt][ks][1] = to_tf32(qk[rowb + d + 4]);
        }
    }
    __syncthreads();   // xs ready

    // GEMM1: this warp's 32m x 32j S tile via 32 mma
    int mw = mbase + g * 32;
    float C[2][4][4];
    #pragma unroll
    for (int mt = 0; mt < 2; mt++)
        #pragma unroll
        for (int jt = 0; jt < 4; jt++)
            #pragma unroll
            for (int e = 0; e < 4; e++) C[mt][jt][e] = 0.f;

    #pragma unroll
    for (int ks = 0; ks < 4; ks++) {
        #pragma unroll
        for (int mt = 0; mt < 2; mt++) {
            int m = mw + mt * 16 + grp;
            int dd = ks * 8 + tig;
            size_t r0 = (brow + m) * 192 + kk * 32 + dd;
            size_t r1 = (brow + m + 8) * 192 + kk * 32 + dd;
            unsigned int A[4];
            A[0] = to_tf32(qk[r0]);
            A[1] = to_tf32(qk[r1]);
            A[2] = to_tf32(qk[r0 + 4]);
            A[3] = to_tf32(qk[r1 + 4]);
            #pragma unroll
            for (int jt = 0; jt < 4; jt++)
                MMA_TF32(C[mt][jt], A, Bf[jt][ks]);
        }
    }

    // elementwise: p = exp(s*scale + bias); pc = p*cheb; denominators
    float sden[4][2];
    #pragma unroll
    for (int jt = 0; jt < 4; jt++) { sden[jt][0] = 0.f; sden[jt][1] = 0.f; }

    #pragma unroll
    for (int mt = 0; mt < 2; mt++) {
        int mg0 = mw + mt * 16 + grp;
        #pragma unroll
        for (int jt = 0; jt < 4; jt++) {
            int jg = j0 + jt * 8 + 2 * tig;
            ulonglong2 bc0 = *(const ulonglong2*)&g_bc[kbase + (size_t)mg0 * 1024 + jg];
            ulonglong2 bc1 = *(const ulonglong2*)&g_bc[kbase + (size_t)(mg0 + 8) * 1024 + jg];
            float bias, cp;
            unpk(bc0.x, bias, cp);
            float p0 = __expf(C[mt][jt][0] * SCALE + bias); sden[jt][0] += p0; float pc0 = p0 * cp;
            unpk(bc0.y, bias, cp);
            float p1 = __expf(C[mt][jt][1] * SCALE + bias); sden[jt][1] += p1; float pc1 = p1 * cp;
            unpk(bc1.x, bias, cp);
            float p2 = __expf(C[mt][jt][2] * SCALE + bias); sden[jt][0] += p2; float pc2 = p2 * cp;
            unpk(bc1.y, bias, cp);
            float p3 = __expf(C[mt][jt][3] * SCALE + bias); sden[jt][1] += p3; float pc3 = p3 * cp;
            int ml = mt * 16 + grp;
            int jl = jt * 8 + 2 * tig;
            *(float2*)&pcs[g][ml][jl]     = make_float2(pc0, pc1);
            *(float2*)&pcs[g][ml + 8][jl] = make_float2(pc2, pc3);
        }
    }

    // reduce denominators over grp (threads sharing same tig)
    #pragma unroll
    for (int jt = 0; jt < 4; jt++)
        #pragma unroll
        for (int cc = 0; cc < 2; cc++) {
            float v = sden[jt][cc];
            v += __shfl_xor_sync(0xFFFFFFFFu, v, 4);
            v += __shfl_xor_sync(0xFFFFFFFFu, v, 8);
            v += __shfl_xor_sync(0xFFFFFFFFu, v, 16);
            sden[jt][cc] = v;
        }
    if (grp == 0) {
        #pragma unroll
        for (int jt = 0; jt < 4; jt++) {
            r_sm[g][jt * 8 + 2 * tig]     = sden[jt][0];
            r_sm[g][jt * 8 + 2 * tig + 1] = sden[jt][1];
        }
    }
    __syncwarp();

    // PV: lane = j, accumulate over this warp's 32 m
    unsigned long long acc[6];
    #pragma unroll
    for (int i = 0; i < 6; i++) acc[i] = 0ull;
    #pragma unroll 4
    for (int m = 0; m < 32; m++) {
        float pcv = pcs[g][m][lane];
        unsigned long long wp = pk2(pcv, pcv);
        const unsigned long long* xr = (const unsigned long long*)&xs[g * 32 + m][0];
        #pragma unroll
        for (int i = 0; i < 6; i++) acc[i] = ffma2(wp, xr[i], acc[i]);
    }

    // merge 8 warp-partials (reuse pcs region for r_acc AFTER all PV done)
    __syncthreads();
    unsigned long long* r_acc = (unsigned long long*)&pcs[0][0][0];   // [8*32][6]
    #pragma unroll
    for (int i = 0; i < 6; i++) r_acc[(g * 32 + lane) * 6 + i] = acc[i];
    __syncthreads();
    if (g == 0) {
        float S = 0.f;
        unsigned long long o[6];
        #pragma unroll
        for (int i = 0; i < 6; i++) o[i] = 0ull;
        #pragma unroll
        for (int q = 0; q < 8; q++) {
            S += r_sm[q][lane];
            #pragma unroll
            for (int i = 0; i < 6; i++) o[i] = add2(o[i], r_acc[(q * 32 + lane) * 6 + i]);
        }
        int jidx = ((b * 3 + kk) << 10) + j0 + lane;
        unsigned long long* pp = g_part + (size_t)quarter * 7 * 49152;
        #pragma unroll
        for (int i = 0; i < 6; i++) pp[i * 49152 + jidx] = o[i];
        pp[6 * 49152 + jidx] = pk2(S, S);
    }
}

// ---------------- K4b: merge the four m-quarters, normalize ----------------
__global__ void k_smerge() {
    int jidx = blockIdx.x * 256 + threadIdx.x;   // 49152
    unsigned long long o[6];
    float S = 0.f;
    #pragma unroll
    for (int i = 0; i < 6; i++) o[i] = 0ull;
    #pragma unroll
    for (int q = 0; q < 4; q++) {
        const unsigned long long* pp = g_part + (size_t)q * 7 * 49152;
        float sl, sh; unpk(pp[6 * 49152 + jidx], sl, sh);
        S += sl;
        #pragma unroll
        for (int i = 0; i < 6; i++) o[i] = add2(o[i], pp[i * 49152 + jidx]);
    }
    float inv = 1.f / S;
    unsigned long long ip = pk2(inv, inv);
    unsigned long long* rp = (unsigned long long*)g_rhs + (size_t)jidx * 6;
    #pragma unroll
    for (int i = 0; i < 6; i++) rp[i] = mul2(o[i], ip);
}

// ---------------- K6: Theta contraction + GTUs + fcmy + residual + final LN (2-pass, __ldg weights) ----------------
__global__ void __launch_bounds__(256, 2) k_gtu(
    const float* __restrict__ x, const float* __restrict__ Theta,
    const float* __restrict__ b3, const float* __restrict__ b5, const float* __restrict__ b7,
    const float* __restrict__ rcw, const float* __restrict__ rcb,
    const float* __restrict__ fcw, const float* __restrict__ fcb,
    const float* __restrict__ gf, const float* __restrict__ bfin,
    float* __restrict__ out) {
    int n0 = blockIdx.x * 8; int b = blockIdx.y;
    int tid = threadIdx.x; int c = tid & 31; int p = tid >> 5; int n = n0 + p;
    __shared__ unsigned long long Xp[8][32][12];
    __shared__ float Vs[8][32][12];
    __shared__ unsigned long long fcw2[24][6];

    if (tid < 144) {
        int w = tid / 6, t2 = tid % 6;
        fcw2[w][t2] = pk2(fcw[w * 12 + 2 * t2], fcw[w * 12 + 2 * t2 + 1]);
    }

    {
        float th0 = Theta[c], th1 = Theta[32 + c], th2 = Theta[64 + c];
        const float* r0 = g_rhs + (((size_t)b * 3 + 0) * 1024 + n) * 12;
        const float* r1 = g_rhs + (((size_t)b * 3 + 1) * 1024 + n) * 12;
        const float* r2 = g_rhs + (((size_t)b * 3 + 2) * 1024 + n) * 12;
        #pragma unroll
        for (int t = 0; t < 12; t++) {
            float v = r0[t] * th0 + r1[t] * th1 + r2[t] * th2;
            v = fmaxf(v, 0.f);
            Xp[p][c][t] = pk2(v, v);
        }
    }
    __syncthreads();

    // v2 accumulates fcmy across both passes
    unsigned long long v2[6];
    {
        const unsigned long long* fcb2 = (const unsigned long long*)fcb;
        #pragma unroll
        for (int t2 = 0; t2 < 6; t2++) v2[t2] = fcb2[t2];
    }

    // ---- pass 1: gtu3 (w 0..9) + gtu7 (w 18..23), 16 accumulators ----
    {
        unsigned long long yA[16];
        unsigned long long i3 = pk2(b3[c], b3[c + 32]);
        unsigned long long i7 = pk2(b7[c], b7[c + 32]);
        #pragma unroll
        for (int w = 0; w < 10; w++) yA[w] = i3;
        #pragma unroll
        for (int w = 0; w < 6; w++)  yA[10 + w] = i7;

        for (int ci = 0; ci < 32; ci++) {
            unsigned long long Xr[12];
            #pragma unroll
            for (int t = 0; t < 12; t++) Xr[t] = Xp[p][ci][t];
            const unsigned long long* wr = g_Wr2 + (size_t)ci * 15 * 32 + c;
            #pragma unroll
            for (int dt = 0; dt < 3; dt++) {
                unsigned long long wv = __ldg(&wr[dt * 32]);
                #pragma unroll
                for (int w = 0; w < 10; w++) yA[w] = ffma2(Xr[w + dt], wv, yA[w]);
            }
            #pragma unroll
            for (int dt = 0; dt < 7; dt++) {
                unsigned long long wv = __ldg(&wr[(8 + dt) * 32]);
                #pragma unroll
                for (int w = 0; w < 6; w++) yA[10 + w] = ffma2(Xr[w + dt], wv, yA[10 + w]);
            }
        }
        #pragma unroll
        for (int w = 0; w < 16; w++) {
            float ya, yb; unpk(yA[w], ya, yb);
            float tv = 1.f - 2.f / (__expf(2.f * ya) + 1.f);
            float sg = 1.f / (1.f + __expf(-yb));
            float gv = tv * sg;
            unsigned long long gp = pk2(gv, gv);
            int row = (w < 10) ? w : (8 + w);   // w 10..15 -> rows 18..23
            #pragma unroll
            for (int t2 = 0; t2 < 6; t2++) v2[t2] = ffma2(gp, fcw2[row][t2], v2[t2]);
        }
    }

    // ---- pass 2: gtu5 (w 10..17), 8 accumulators ----
    {
        unsigned long long yB[8];
        unsigned long long i5 = pk2(b5[c], b5[c + 32]);
        #pragma unroll
        for (int w = 0; w < 8; w++) yB[w] = i5;

        for (int ci = 0; ci < 32; ci++) {
            unsigned long long Xr[12];
            #pragma unroll
            for (int t = 0; t < 12; t++) Xr[t] = Xp[p][ci][t];
            const unsigned long long* wr = g_Wr2 + (size_t)ci * 15 * 32 + c;
            #pragma unroll
            for (int dt = 0; dt < 5; dt++) {
                unsigned long long wv = __ldg(&wr[(3 + dt) * 32]);
                #pragma unroll
                for (int w = 0; w < 8; w++) yB[w] = ffma2(Xr[w + dt], wv, yB[w]);
            }
        }
        #pragma unroll
        for (int w = 0; w < 8; w++) {
            float ya, yb; unpk(yB[w], ya, yb);
            float tv = 1.f - 2.f / (__expf(2.f * ya) + 1.f);
            float sg = 1.f / (1.f + __expf(-yb));
            float gv = tv * sg;
            unsigned long long gp = pk2(gv, gv);
            #pragma unroll
            for (int t2 = 0; t2 < 6; t2++) v2[t2] = ffma2(gp, fcw2[10 + w][t2], v2[t2]);
        }
    }

    float rw = rcw[c], rb = rcb[c];
    const unsigned long long* xp2 = (const unsigned long long*)x + ((size_t)b * 1024 + n) * 6;
    #pragma unroll
    for (int t2 = 0; t2 < 6; t2++) {
        float va, vb; unpk(v2[t2], va, vb);
        float xa, xb; unpk(xp2[t2], xa, xb);
        va = fmaxf(va, 0.f); vb = fmaxf(vb, 0.f);
        Vs[p][c][2 * t2]     = fmaxf(xa * rw + rb + va, 0.f);
        Vs[p][c][2 * t2 + 1] = fmaxf(xb * rw + rb + vb, 0.f);
    }
    __syncthreads();

    if (tid < 96) {
        int p2 = tid / 12, t2 = tid % 12;
        float s = 0.f, s2 = 0.f;
        #pragma unroll
        for (int cc = 0; cc < 32; cc++) { float v = Vs[p2][cc][t2]; s += v; s2 += v * v; }
        float mu = s * (1.f / 32.f);
        float var = s2 * (1.f / 32.f) - mu * mu;
        float rstd = rsqrtf(var + 1e-5f);
        float* op = out + (((size_t)b * 1024 + n0 + p2) * 32) * 12 + t2;
        #pragma unroll
        for (int cc = 0; cc < 32; cc++)
            op[cc * 12] = (Vs[p2][cc][t2] - mu) * rstd * gf[cc] + bfin[cc];
    }
}

// ---------------- launch ----------------
extern "C" void kernel_launch(void* const* d_in, const int* in_sizes, int n_in,
                              void* d_out, int out_size) {
    const float* x     = (const float*)d_in[0];
    const float* resa  = (const float*)d_in[1];
    const float* peT   = (const float*)d_in[2];
    const float* gT    = (const float*)d_in[3];
    const float* bT    = (const float*)d_in[4];
    const float* WQt   = (const float*)d_in[5];
    const float* WKt   = (const float*)d_in[6];
    const float* WVt   = (const float*)d_in[7];
    const float* fct   = (const float*)d_in[8];
    const float* pcw   = (const float*)d_in[9];
    const float* pcb   = (const float*)d_in[10];
    const float* peS   = (const float*)d_in[11];
    const float* gS    = (const float*)d_in[12];
    const float* bS    = (const float*)d_in[13];
    const float* WQs   = (const float*)d_in[14];
    const float* WKs   = (const float*)d_in[15];
    const float* cheb  = (const float*)d_in[16];
    const float* adj   = (const float*)d_in[17];
    const float* cmask = (const float*)d_in[18];
    const float* Theta = (const float*)d_in[19];
    const float* w3    = (const float*)d_in[20];
    const float* b3    = (const float*)d_in[21];
    const float* w5    = (const float*)d_in[22];
    const float* b5    = (const float*)d_in[23];
    const float* w7    = (const float*)d_in[24];
    const float* b7    = (const float*)d_in[25];
    const float* rcw   = (const float*)d_in[26];
    const float* rcb   = (const float*)d_in[27];
    const float* fcw   = (const float*)d_in[28];
    const float* fcb   = (const float*)d_in[29];
    const float* gf    = (const float*)d_in[30];
    const float* bf    = (const float*)d_in[31];

    float* out  = (float*)d_out;
    float* reat = out + (size_t)16 * 1024 * 32 * 12;  // re_At after main output

    k_temporal_ln<<<16, 1024>>>(x, peT, gT, bT);
    k_qkv<<<dim3(16, 4), 288>>>(WQt, WKt, WVt);
    k_tattn<<<48, 384>>>(resa, reat);
    k_tatout<<<96, 512>>>(fct);
    k_prep<<<6204, 256>>>(adj, cmask, cheb, w3, w5, w7);
    k_semx<<<2048, 256>>>(pcw, pcb, peS, gS, bS);
    k_qks_gemm<<<128, 256>>>(WQs, WKs);
    k_spatial<<<dim3(32, 3, 64), 256>>>(x);
    k_smerge<<<192, 256>>>();
    k_gtu<<<dim3(128, 16), 256>>>(x, Theta, b3, b5, b7, rcw, rcb, fcw, fcb, gf, bf, out);
}